// round 3
// baseline (speedup 1.0000x reference)
#include <cuda_runtime.h>
#include <math.h>

#define N_ 8
#define S_ 1024
#define F_ 64
#define E_ 512
#define H_ 8
#define HD_ 64
#define O_ 64
#define L_ 6
#define FF_ 2048
#define NS_ (N_*S_)

// ---------------- scratch (no allocations allowed) ----------------
__device__ float g_h[NS_*E_];       // running hidden state (n,s,e)
__device__ float g_q[NS_*E_];       // (n,h,s,d)
__device__ float g_k[NS_*E_];
__device__ float g_v[NS_*E_];
__device__ float g_attn[NS_*E_];    // attention output (n,s,e)
__device__ float g_buf[NS_*E_];     // pre-LN sum
__device__ float g_hx[NS_*E_];      // post-LN1
__device__ float g_ff[NS_*FF_];     // FFN hidden

// ---------------- kernel 1: embed = relu(x @ W_first + b) + pos ----------------
__global__ __launch_bounds__(512) void embed_kernel(
    const float* __restrict__ x, const float* __restrict__ W,
    const float* __restrict__ b, const float* __restrict__ pos)
{
    int ns = blockIdx.x;                 // (n,s) row
    int n = ns >> 10, s = ns & (S_-1);
    int e = threadIdx.x;                 // 512 threads = E
    __shared__ float xs[F_];
    if (e < F_) xs[e] = x[(size_t)n*F_*S_ + (size_t)e*S_ + s];
    __syncthreads();
    float acc = b[e];
    #pragma unroll 16
    for (int f = 0; f < F_; ++f)
        acc = fmaf(xs[f], W[f*E_ + e], acc);
    acc = fmaxf(acc, 0.0f) + pos[s*E_ + e];
    g_h[(size_t)ns*E_ + e] = acc;
}

// ---------------- kernel 2: per-head QKV projection ----------------
// q[n,s,h,:] = h[n,s,h*64:+64] @ Wq + bq   (same 64x64 W for all heads)
// outputs in (n,h,s,d) layout for attention
__global__ __launch_bounds__(512) void qkv_kernel(
    const float* __restrict__ Wq, const float* __restrict__ bq,
    const float* __restrict__ Wk, const float* __restrict__ bk,
    const float* __restrict__ Wv, const float* __restrict__ bv)
{
    int ns0 = blockIdx.x * 4;            // 4 (n,s) rows per block
    int t = threadIdx.x;
    int hh = t >> 6, dp = t & 63;
    __shared__ float hs[4][E_];
    #pragma unroll
    for (int r = 0; r < 4; ++r)
        hs[r][t] = g_h[(size_t)(ns0 + r)*E_ + t];
    __syncthreads();
    float aq[4], ak[4], av[4];
    float bqv = bq[dp], bkv = bk[dp], bvv = bv[dp];
    #pragma unroll
    for (int r = 0; r < 4; ++r) { aq[r]=bqv; ak[r]=bkv; av[r]=bvv; }
    #pragma unroll 4
    for (int d = 0; d < HD_; ++d) {
        float wq = Wq[d*HD_+dp], wk = Wk[d*HD_+dp], wv = Wv[d*HD_+dp];
        #pragma unroll
        for (int r = 0; r < 4; ++r) {
            float hv = hs[r][hh*HD_ + d];
            aq[r] = fmaf(hv, wq, aq[r]);
            ak[r] = fmaf(hv, wk, ak[r]);
            av[r] = fmaf(hv, wv, av[r]);
        }
    }
    #pragma unroll
    for (int r = 0; r < 4; ++r) {
        int ns = ns0 + r;
        int n = ns >> 10, s = ns & (S_-1);
        size_t o = ((size_t)(n*H_ + hh)*S_ + s)*HD_ + dp;
        g_q[o] = aq[r]; g_k[o] = ak[r]; g_v[o] = av[r];
    }
}

// ---------------- kernel 3: flash attention (fp32, online softmax) ----------------
// block = 256 threads handles one (n,h) and a 64-query tile; Tk = 32.
// thread (ty,tx) in 16x16; rows ty+16i, S-cols tx+16j (j<2), O-cols tx+16j (j<4)
__global__ __launch_bounds__(256) void attn_kernel()
{
    __shared__ float Qs[64][64];   // broadcast reads -> no pad needed
    __shared__ float Ks[32][65];   // strided-tx reads -> odd pitch
    __shared__ float Vs[32][64];   // stride-1 reads
    __shared__ float Ps[64][33];   // broadcast reads, pad for conflict-free store

    int bid = blockIdx.x;
    int qt = bid & 15;             // 16 q-tiles of 64
    int nh = bid >> 4;             // 0..63 = n*H + h
    const float* Qb = g_q + (size_t)nh*S_*HD_ + (size_t)qt*64*HD_;
    const float* Kb = g_k + (size_t)nh*S_*HD_;
    const float* Vb = g_v + (size_t)nh*S_*HD_;

    int tid = threadIdx.x;
    int tx = tid & 15, ty = tid >> 4;
    const float isc = 0.044194173824159216f;   // 1/sqrt(E) -- module scales by sqrt(embed)

    // load + pre-scale Q tile (4096 contiguous floats)
    for (int idx = tid*4; idx < 4096; idx += 1024) {
        float4 t4 = *(const float4*)(Qb + idx);
        int r = idx >> 6, c = idx & 63;
        Qs[r][c]   = t4.x*isc; Qs[r][c+1] = t4.y*isc;
        Qs[r][c+2] = t4.z*isc; Qs[r][c+3] = t4.w*isc;
    }

    float o[4][4] = {};
    float m[4], l[4];
    #pragma unroll
    for (int i = 0; i < 4; ++i) { m[i] = -1e30f; l[i] = 0.0f; }

    for (int kt = 0; kt < 32; ++kt) {
        __syncthreads();           // previous PV done before overwriting Ks/Vs/Ps
        {
            const float* kp = Kb + kt*32*64;
            const float* vp = Vb + kt*32*64;
            int idx = tid*8;
            #pragma unroll
            for (int u = 0; u < 2; ++u) {
                int id = idx + u*4;
                float4 k4 = *(const float4*)(kp + id);
                float4 v4 = *(const float4*)(vp + id);
                int r = id >> 6, c = id & 63;
                Ks[r][c]=k4.x; Ks[r][c+1]=k4.y; Ks[r][c+2]=k4.z; Ks[r][c+3]=k4.w;
                *(float4*)&Vs[r][c] = v4;
            }
        }
        __syncthreads();

        // S = Q K^T  (64x32 tile; 4x2 per thread)
        float s[4][2] = {};
        #pragma unroll 4
        for (int d = 0; d < 64; ++d) {
            float q0=Qs[ty][d], q1=Qs[ty+16][d], q2=Qs[ty+32][d], q3=Qs[ty+48][d];
            float k0=Ks[tx][d], k1=Ks[tx+16][d];
            s[0][0]=fmaf(q0,k0,s[0][0]); s[1][0]=fmaf(q1,k0,s[1][0]);
            s[2][0]=fmaf(q2,k0,s[2][0]); s[3][0]=fmaf(q3,k0,s[3][0]);
            s[0][1]=fmaf(q0,k1,s[0][1]); s[1][1]=fmaf(q1,k1,s[1][1]);
            s[2][1]=fmaf(q2,k1,s[2][1]); s[3][1]=fmaf(q3,k1,s[3][1]);
        }

        // online softmax per row (row lives in one 16-lane shfl group)
        #pragma unroll
        for (int i = 0; i < 4; ++i) {
            float mloc = fmaxf(s[i][0], s[i][1]);
            #pragma unroll
            for (int off = 8; off; off >>= 1)
                mloc = fmaxf(mloc, __shfl_xor_sync(0xffffffffu, mloc, off));
            float mnew = fmaxf(m[i], mloc);
            float alpha = __expf(m[i] - mnew);
            float p0 = __expf(s[i][0] - mnew);
            float p1 = __expf(s[i][1] - mnew);
            m[i] = mnew;
            float ls = p0 + p1;
            #pragma unroll
            for (int off = 8; off; off >>= 1)
                ls += __shfl_xor_sync(0xffffffffu, ls, off);
            l[i] = l[i]*alpha + ls;
            #pragma unroll
            for (int j = 0; j < 4; ++j) o[i][j] *= alpha;
            Ps[ty+16*i][tx]    = p0;
            Ps[ty+16*i][tx+16] = p1;
        }
        __syncthreads();

        // O += P V  (64x64; 4x4 per thread)
        #pragma unroll 4
        for (int k = 0; k < 32; ++k) {
            float p0=Ps[ty][k], p1=Ps[ty+16][k], p2=Ps[ty+32][k], p3=Ps[ty+48][k];
            float v0=Vs[k][tx], v1=Vs[k][tx+16], v2=Vs[k][tx+32], v3=Vs[k][tx+48];
            o[0][0]=fmaf(p0,v0,o[0][0]); o[0][1]=fmaf(p0,v1,o[0][1]); o[0][2]=fmaf(p0,v2,o[0][2]); o[0][3]=fmaf(p0,v3,o[0][3]);
            o[1][0]=fmaf(p1,v0,o[1][0]); o[1][1]=fmaf(p1,v1,o[1][1]); o[1][2]=fmaf(p1,v2,o[1][2]); o[1][3]=fmaf(p1,v3,o[1][3]);
            o[2][0]=fmaf(p2,v0,o[2][0]); o[2][1]=fmaf(p2,v1,o[2][1]); o[2][2]=fmaf(p2,v2,o[2][2]); o[2][3]=fmaf(p2,v3,o[2][3]);
            o[3][0]=fmaf(p3,v0,o[3][0]); o[3][1]=fmaf(p3,v1,o[3][1]); o[3][2]=fmaf(p3,v2,o[3][2]); o[3][3]=fmaf(p3,v3,o[3][3]);
        }
    }

    // write O in (n,s,e) layout
    int n = nh >> 3, hh = nh & 7;
    float* Ob = g_attn + ((size_t)n*S_ + qt*64)*E_ + hh*HD_;
    #pragma unroll
    for (int i = 0; i < 4; ++i) {
        float invl = 1.0f / l[i];
        int r = ty + 16*i;
        #pragma unroll
        for (int j = 0; j < 4; ++j)
            Ob[(size_t)r*E_ + tx + 16*j] = o[i][j]*invl;
    }
}

// ---------------- kernel 4: generic GEMM C = A@B + bias (+R) (+relu) ----------------
// BM=BN=64, BK=16, 256 threads, 4x4 per thread (strided micro-tile)
template<int RELU, int RESID, int FINAL>
__global__ __launch_bounds__(256) void gemm_kernel(
    const float* __restrict__ A, const float* __restrict__ B,
    const float* __restrict__ bias, const float* __restrict__ R,
    float* __restrict__ C, int M, int Nn, int K)
{
    __shared__ float As[16][65];   // transposed A tile
    __shared__ float Bs[16][64];
    int m0 = blockIdx.y * 64, n0 = blockIdx.x * 64;
    int tid = threadIdx.x;
    int tx = tid & 15, ty = tid >> 4;

    int ar = tid >> 2;             // 0..63 row of A tile
    int ac = (tid & 3) * 4;        // k offset
    int br = tid >> 4;             // 0..15 k row of B tile
    int bc = (tid & 15) * 4;
    const float* Ap = A + (size_t)(m0 + ar)*K + ac;
    const float* Bp = B + (size_t)br*Nn + n0 + bc;

    float acc[4][4] = {};
    for (int k0 = 0; k0 < K; k0 += 16) {
        float4 a4 = *(const float4*)(Ap + k0);
        float4 b4 = *(const float4*)(Bp + (size_t)k0*Nn);
        As[ac+0][ar]=a4.x; As[ac+1][ar]=a4.y; As[ac+2][ar]=a4.z; As[ac+3][ar]=a4.w;
        *(float4*)&Bs[br][bc] = b4;
        __syncthreads();
        #pragma unroll
        for (int kk = 0; kk < 16; ++kk) {
            float a[4], b[4];
            #pragma unroll
            for (int i = 0; i < 4; ++i) a[i] = As[kk][ty + 16*i];
            #pragma unroll
            for (int j = 0; j < 4; ++j) b[j] = Bs[kk][tx + 16*j];
            #pragma unroll
            for (int i = 0; i < 4; ++i)
                #pragma unroll
                for (int j = 0; j < 4; ++j)
                    acc[i][j] = fmaf(a[i], b[j], acc[i][j]);
        }
        __syncthreads();
    }
    #pragma unroll
    for (int i = 0; i < 4; ++i) {
        int mrow = m0 + ty + 16*i;
        #pragma unroll
        for (int j = 0; j < 4; ++j) {
            int nn = n0 + tx + 16*j;
            float v = acc[i][j] + bias[nn];
            if (RESID) v += R[(size_t)mrow*Nn + nn];
            if (RELU)  v = fmaxf(v, 0.0f);
            if (FINAL) {
                // out[n, o, s]  where mrow = n*S + s, nn = o
                C[((size_t)(mrow >> 10)*O_ + nn)*S_ + (mrow & (S_-1))] = v;
            } else {
                C[(size_t)mrow*Nn + nn] = v;
            }
        }
    }
}

// ---------------- kernel 5: layernorm over E=512 ----------------
__global__ __launch_bounds__(128) void ln_kernel(
    const float* __restrict__ in, float* __restrict__ out,
    const float* __restrict__ g, const float* __restrict__ b)
{
    int row = blockIdx.x;
    int t = threadIdx.x;                 // 128 threads x 4 elems
    const float* p = in + (size_t)row*E_;
    float v[4], s = 0.0f, sq = 0.0f;
    #pragma unroll
    for (int q = 0; q < 4; ++q) {
        v[q] = p[t + 128*q];
        s += v[q]; sq += v[q]*v[q];
    }
    #pragma unroll
    for (int off = 16; off; off >>= 1) {
        s  += __shfl_xor_sync(0xffffffffu, s,  off);
        sq += __shfl_xor_sync(0xffffffffu, sq, off);
    }
    __shared__ float red[2][4];
    int w = t >> 5;
    if ((t & 31) == 0) { red[0][w] = s; red[1][w] = sq; }
    __syncthreads();
    s  = red[0][0] + red[0][1] + red[0][2] + red[0][3];
    sq = red[1][0] + red[1][1] + red[1][2] + red[1][3];
    float mean = s * (1.0f/E_);
    float var = sq * (1.0f/E_) - mean*mean;
    float inv = rsqrtf(var + 1e-5f);
    float* q_ = out + (size_t)row*E_;
    #pragma unroll
    for (int q = 0; q < 4; ++q) {
        int e = t + 128*q;
        q_[e] = (v[q] - mean)*inv*g[e] + b[e];
    }
}

// ---------------- launch ----------------
extern "C" void kernel_launch(void* const* d_in, const int* in_sizes, int n_in,
                              void* d_out, int out_size)
{
    const float* x       = (const float*)d_in[0];
    const float* W_first = (const float*)d_in[1];
    const float* b_first = (const float*)d_in[2];
    const float* pos_emb = (const float*)d_in[3];
    const float* Wq      = (const float*)d_in[4];
    const float* bq      = (const float*)d_in[5];
    const float* Wk      = (const float*)d_in[6];
    const float* bk      = (const float*)d_in[7];
    const float* Wv      = (const float*)d_in[8];
    const float* bv      = (const float*)d_in[9];
    const float* Wo      = (const float*)d_in[10];
    const float* bo      = (const float*)d_in[11];
    const float* g1      = (const float*)d_in[12];
    const float* be1     = (const float*)d_in[13];
    const float* Wf1     = (const float*)d_in[14];
    const float* bf1     = (const float*)d_in[15];
    const float* Wf2     = (const float*)d_in[16];
    const float* bf2     = (const float*)d_in[17];
    const float* g2      = (const float*)d_in[18];
    const float* be2     = (const float*)d_in[19];
    const float* Wfin    = (const float*)d_in[20];
    const float* bfin    = (const float*)d_in[21];
    (void)in_sizes; (void)n_in; (void)out_size;

    float *h_p, *attn_p, *buf_p, *hx_p, *ff_p;
    cudaGetSymbolAddress((void**)&h_p,   g_h);
    cudaGetSymbolAddress((void**)&attn_p,g_attn);
    cudaGetSymbolAddress((void**)&buf_p, g_buf);
    cudaGetSymbolAddress((void**)&hx_p,  g_hx);
    cudaGetSymbolAddress((void**)&ff_p,  g_ff);

    embed_kernel<<<NS_, 512>>>(x, W_first, b_first, pos_emb);

    for (int i = 0; i < L_; ++i) {
        qkv_kernel<<<NS_/4, 512>>>(Wq + i*HD_*HD_, bq + i*HD_,
                                   Wk + i*HD_*HD_, bk + i*HD_,
                                   Wv + i*HD_*HD_, bv + i*HD_);
        attn_kernel<<<N_*H_*(S_/64), 256>>>();
        // o@Wo + bo + h -> buf ; LN -> hx
        gemm_kernel<0,1,0><<<dim3(E_/64, NS_/64), 256>>>(
            attn_p, Wo + (size_t)i*E_*E_, bo + i*E_, h_p, buf_p, NS_, E_, E_);
        ln_kernel<<<NS_, 128>>>(buf_p, hx_p, g1 + i*E_, be1 + i*E_);
        // relu(hx@Wf1 + bf1) -> ff
        gemm_kernel<1,0,0><<<dim3(FF_/64, NS_/64), 256>>>(
            hx_p, Wf1 + (size_t)i*E_*FF_, bf1 + i*FF_, (const float*)0, ff_p, NS_, FF_, E_);
        // ff@Wf2 + bf2 + hx -> buf ; LN -> h
        gemm_kernel<0,1,0><<<dim3(E_/64, NS_/64), 256>>>(
            ff_p, Wf2 + (size_t)i*FF_*E_, bf2 + i*E_, hx_p, buf_p, NS_, E_, FF_);
        ln_kernel<<<NS_, 128>>>(buf_p, h_p, g2 + i*E_, be2 + i*E_);
    }

    // final pointwise conv: out[n,o,s] = h @ Wfin + bfin
    gemm_kernel<0,0,1><<<dim3(O_/64, NS_/64), 256>>>(
        h_p, Wfin, bfin, (const float*)0, (float*)d_out, NS_, O_, E_);
}